// round 1
// baseline (speedup 1.0000x reference)
#include <cuda_runtime.h>
#include <math.h>

#define BB 8
#define NN 2048
#define EE 128
#define HH 4

// ---------------- scratch (device globals; no runtime allocation) ----------
static __device__ float g_info[(size_t)BB * NN * NN];           // 134 MB
static __device__ float g_emb [(size_t)BB * NN * EE];
static __device__ float g_q   [(size_t)BB * HH * NN * EE];
static __device__ float g_v   [(size_t)BB * HH * NN * EE];
static __device__ float g_mt  [(size_t)BB * HH * NN * EE];      // (info @ v) = (v^T info)^T
static __device__ float g_attn[(size_t)BB * HH * NN * NN];      // 537 MB
static __device__ float g_hcat[(size_t)BB * NN * HH * EE];

// ---------------------------------------------------------------------------
// Generic tiled fp32 GEMM: C[M x Nn] = epi( A[M x K] * op(B) , bias, alpha )
//   TRANSB=1 : B is [Nn x K] row-major  (C = A * B^T)
//   TRANSB=0 : B is [K x Nn] row-major  (C = A * B)
//   EPI: 0 = none, 1 = +bias[n], 2 = tanh(acc*alpha), 3 = relu(acc+bias[n])
// Block tile 128x128, BK=8, 256 threads, 8x8 per thread.
// Requires: M % 128 == 0, Nn % 128 == 0, K % 8 == 0 (true for all stages).
// ---------------------------------------------------------------------------
template <int TRANSB, int EPI>
__global__ void __launch_bounds__(256)
gemm_k(const float* __restrict__ A, size_t sA,
       const float* __restrict__ Bm, size_t sB,
       const float* __restrict__ bias,
       float* __restrict__ C, size_t sC, int ldc,
       int M, int Nn, int K, float alpha)
{
    __shared__ float As[8][132];
    __shared__ float Bs[8][132];

    const int t    = threadIdx.x;
    const int tx   = t & 15;
    const int ty   = t >> 4;
    const int mblk = blockIdx.y * 128;
    const int nblk = blockIdx.x * 128;
    const int z    = blockIdx.z;

    A  += (size_t)z * sA;
    Bm += (size_t)z * sB;
    C  += (size_t)z * sC;

    // global-load mapping: each thread loads one float4 of A (and of B)
    const int arow = t >> 1;        // 0..127 (tile row)
    const int acol = (t & 1) * 4;   // 0 or 4 (k offset)
    const float* Aptr = A + (size_t)(mblk + arow) * K + acol;

    const float* Bptr;
    int brow = 0, bcol = 0;
    if (TRANSB) {
        Bptr = Bm + (size_t)(nblk + arow) * K + acol;   // B [Nn x K]
    } else {
        brow = t >> 5;              // 0..7 (k)
        bcol = (t & 31) * 4;        // 0..124 (n)
        Bptr = Bm + (size_t)brow * Nn + nblk + bcol;    // B [K x Nn]
    }

    float acc[8][8];
#pragma unroll
    for (int i = 0; i < 8; i++)
#pragma unroll
        for (int j = 0; j < 8; j++) acc[i][j] = 0.f;

    for (int kk = 0; kk < K; kk += 8) {
        float4 av = *(const float4*)(Aptr + kk);
        float4 bv;
        if (TRANSB) bv = *(const float4*)(Bptr + kk);
        else        bv = *(const float4*)(Bptr + (size_t)kk * Nn);

        __syncthreads();   // previous tile consumed
        As[acol + 0][arow] = av.x;
        As[acol + 1][arow] = av.y;
        As[acol + 2][arow] = av.z;
        As[acol + 3][arow] = av.w;
        if (TRANSB) {
            Bs[acol + 0][arow] = bv.x;
            Bs[acol + 1][arow] = bv.y;
            Bs[acol + 2][arow] = bv.z;
            Bs[acol + 3][arow] = bv.w;
        } else {
            *(float4*)&Bs[brow][bcol] = bv;
        }
        __syncthreads();

#pragma unroll
        for (int k = 0; k < 8; k++) {
            float a[8], b[8];
            *(float4*)&a[0] = *(const float4*)&As[k][ty * 8];
            *(float4*)&a[4] = *(const float4*)&As[k][ty * 8 + 4];
            *(float4*)&b[0] = *(const float4*)&Bs[k][tx * 8];
            *(float4*)&b[4] = *(const float4*)&Bs[k][tx * 8 + 4];
#pragma unroll
            for (int i = 0; i < 8; i++)
#pragma unroll
                for (int j = 0; j < 8; j++)
                    acc[i][j] = fmaf(a[i], b[j], acc[i][j]);
        }
    }

    // epilogue
    float bfrag[8];
    if (EPI == 1 || EPI == 3) {
#pragma unroll
        for (int j = 0; j < 8; j++) bfrag[j] = __ldg(&bias[nblk + tx * 8 + j]);
    }

#pragma unroll
    for (int i = 0; i < 8; i++) {
        size_t row = (size_t)(mblk + ty * 8 + i) * ldc + nblk + tx * 8;
        float o[8];
#pragma unroll
        for (int j = 0; j < 8; j++) {
            float vv = acc[i][j];
            if (EPI == 1) vv += bfrag[j];
            else if (EPI == 2) vv = tanhf(vv * alpha);
            else if (EPI == 3) { vv += bfrag[j]; vv = vv > 0.f ? vv : 0.f; }
            o[j] = vv;
        }
        *(float4*)(C + row)     = make_float4(o[0], o[1], o[2], o[3]);
        *(float4*)(C + row + 4) = make_float4(o[4], o[5], o[6], o[7]);
    }
}

// ---------------------------------------------------------------------------
extern "C" void kernel_launch(void* const* d_in, const int* in_sizes, int n_in,
                              void* d_out, int out_size)
{
    const float* x   = (const float*)d_in[0];   // [B,N,DF]
    const float* W1  = (const float*)d_in[1];   // [E,N]
    const float* b1  = (const float*)d_in[2];   // [E]
    const float* wqW = (const float*)d_in[3];   // [H,E,E]
    const float* wqb = (const float*)d_in[4];   // [H,E]
    // d_in[5], d_in[6]: wk_W / wk_b — dead in the reference (k unused); skipped
    const float* wvW = (const float*)d_in[7];   // [H,E,E]
    const float* wvb = (const float*)d_in[8];   // [H,E]
    const float* W2  = (const float*)d_in[9];   // [E, H*E]
    const float* b2  = (const float*)d_in[10];  // [E]
    float* out = (float*)d_out;

    float *info, *emb, *q, *v, *mt, *attn, *hcat;
    cudaGetSymbolAddress((void**)&info, g_info);
    cudaGetSymbolAddress((void**)&emb,  g_emb);
    cudaGetSymbolAddress((void**)&q,    g_q);
    cudaGetSymbolAddress((void**)&v,    g_v);
    cudaGetSymbolAddress((void**)&mt,   g_mt);
    cudaGetSymbolAddress((void**)&attn, g_attn);
    cudaGetSymbolAddress((void**)&hcat, g_hcat);

    const dim3 blk(256);
    const float alpha = 0.08838834764831843f;   // 1/sqrt(128)

    // S1: info[b] = x_b @ x_b^T          [2048x2048], K=128
    gemm_k<1, 0><<<dim3(16, 16, BB), blk>>>(
        x, (size_t)NN * EE, x, (size_t)NN * EE, nullptr,
        info, (size_t)NN * NN, NN, NN, NN, EE, 0.f);

    // S2: emb[b] = info_b @ W1^T + b1    [2048x128], K=2048
    gemm_k<1, 1><<<dim3(1, 16, BB), blk>>>(
        info, (size_t)NN * NN, W1, 0, b1,
        emb, (size_t)NN * EE, EE, NN, EE, NN, 0.f);

    // S3: q,v per head: [2048x128] = emb_b @ W_h^T + b_h   K=128
    for (int h = 0; h < HH; h++) {
        gemm_k<1, 1><<<dim3(1, 16, BB), blk>>>(
            emb, (size_t)NN * EE, wqW + (size_t)h * EE * EE, 0, wqb + h * EE,
            q + (size_t)h * NN * EE, (size_t)HH * NN * EE, EE, NN, EE, EE, 0.f);
        gemm_k<1, 1><<<dim3(1, 16, BB), blk>>>(
            emb, (size_t)NN * EE, wvW + (size_t)h * EE * EE, 0, wvb + h * EE,
            v + (size_t)h * NN * EE, (size_t)HH * NN * EE, EE, NN, EE, EE, 0.f);
    }

    // S4: mt[b,h] = info_b @ v_bh   (= (v^T info)^T, info symmetric)  K=2048
    for (int h = 0; h < HH; h++) {
        gemm_k<0, 0><<<dim3(1, 16, BB), blk>>>(
            info, (size_t)NN * NN,
            v + (size_t)h * NN * EE, (size_t)HH * NN * EE, nullptr,
            mt + (size_t)h * NN * EE, (size_t)HH * NN * EE, EE, NN, EE, NN, 0.f);
    }

    // S5: attn[z] = tanh( (q_z @ mt_z^T) / sqrt(E) )   [2048x2048], K=128, z=b*H+h
    gemm_k<1, 2><<<dim3(16, 16, BB * HH), blk>>>(
        q, (size_t)NN * EE, mt, (size_t)NN * EE, nullptr,
        attn, (size_t)NN * NN, NN, NN, NN, EE, alpha);

    // S6: hcat[b, :, h*128:(h+1)*128] = attn_bh @ v_bh   K=2048
    for (int h = 0; h < HH; h++) {
        gemm_k<0, 0><<<dim3(1, 16, BB), blk>>>(
            attn + (size_t)h * NN * NN, (size_t)HH * NN * NN,
            v + (size_t)h * NN * EE, (size_t)HH * NN * EE, nullptr,
            hcat + (size_t)h * EE, (size_t)NN * HH * EE, HH * EE, NN, EE, NN, 0.f);
    }

    // S7: out[b] = relu( hcat_b @ W2^T + b2 )   [2048x128], K=512
    gemm_k<1, 3><<<dim3(1, 16, BB), blk>>>(
        hcat, (size_t)NN * HH * EE, W2, 0, b2,
        out, (size_t)NN * EE, EE, NN, EE, HH * EE, 0.f);
}